// round 4
// baseline (speedup 1.0000x reference)
#include <cuda_runtime.h>
#include <cuda_fp16.h>

#define IH 256
#define IW 256
#define NPIX (IH * IW)          // 65536
#define NMAPS 88                // 8 * (10 + 1)
#define SRC_ELEMS (NPIX * 3)    // 196608

#define QSTRIDE 132             // quads per row (padded)
#define QROWS 129
#define COPYSZ (QROWS * QSTRIDE)    // 17028 quads per parity copy

// One quad = 2x2 pixels, each pixel 4 fp16 (r,g,b,0) = 32 bytes, 32B-aligned.
// [0..3]=(r0,c0) NW, [4..7]=(r0,c1) NE, [8..11]=(r1,c0) SW, [12..15]=(r1,c1) SE.
// Copy (py,px): quad (ky,kx) covers rows (2ky-py, 2ky-py+1), cols (2kx-px, 2kx-px+1).
// OOB pixels stored as ZERO (bakes in the reference's corner masks).
struct __align__(32) Quad { uint4 a, b; };
__device__ Quad g_quads[4 * COPYSZ];   // ~2.18 MB, L2-resident

__device__ __forceinline__ void px_fetch(const float* __restrict__ s, int r, int c, __half* out) {
    if ((unsigned)r < IH && (unsigned)c < IW) {
        const float* p = s + (r * IW + c) * 3;
        out[0] = __float2half(p[0]);
        out[1] = __float2half(p[1]);
        out[2] = __float2half(p[2]);
        out[3] = __float2half(0.f);
    } else {
        out[0] = out[1] = out[2] = out[3] = __float2half(0.f);
    }
}

__global__ void pack_src_kernel(const float* __restrict__ src) {
    int t = blockIdx.x * blockDim.x + threadIdx.x;
    if (t >= 4 * COPYSZ) return;
    int c   = t / COPYSZ;
    int rem = t % COPYSZ;
    int ky = rem / QSTRIDE;
    int kx = rem % QSTRIDE;
    int py = c >> 1, px = c & 1;
    int r0 = 2 * ky - py;
    int c0 = 2 * kx - px;

    __align__(32) __half h[16];
    px_fetch(src, r0,     c0,     h + 0);
    px_fetch(src, r0,     c0 + 1, h + 4);
    px_fetch(src, r0 + 1, c0,     h + 8);
    px_fetch(src, r0 + 1, c0 + 1, h + 12);
    g_quads[t] = *reinterpret_cast<Quad*>(h);
}

__device__ __forceinline__ float2 h2f(float v) {
    __half2 h = *reinterpret_cast<__half2*>(&v);
    return __half22float2(h);
}

// One thread = 2 consecutive pixels. 88*65536/2 = 2,883,584 threads (11264 x 256).
__global__ void __launch_bounds__(256) deform_kernel(
    const float* __restrict__ motions, float* __restrict__ out) {
    int t = blockIdx.x * blockDim.x + threadIdx.x;

    // motions for 2 pixels: one coalesced 16B streaming load
    float4 m = __ldcs(&reinterpret_cast<const float4*>(motions)[t]);

    float gx[2] = {m.x, m.z};
    float gy[2] = {m.y, m.w};

    float fx[2], fy[2];
    const Quad* qp[2];
#pragma unroll
    for (int s = 0; s < 2; s++) {
        float x = fmaf(gx[s], 128.f, 127.5f);   // [-0.5, 255.5)
        float y = fmaf(gy[s], 128.f, 127.5f);
        int xw = __float2int_rd(x);     // [-1, 255]
        int yn = __float2int_rd(y);     // [-1, 255]
        fx[s] = x - (float)xw;
        fy[s] = y - (float)yn;
        int py = yn & 1, px = xw & 1;
        int ky = (yn + py) >> 1;        // [0,128]
        int kx = (xw + px) >> 1;        // [0,128]
        qp[s] = &g_quads[((py << 1) | px) * COPYSZ + ky * QSTRIDE + kx];
    }

    // Two independent 256-bit gathers, issued back-to-back.
    float q[2][8];
#pragma unroll
    for (int s = 0; s < 2; s++) {
        asm("ld.global.nc.v8.f32 {%0,%1,%2,%3,%4,%5,%6,%7}, [%8];"
            : "=f"(q[s][0]), "=f"(q[s][1]), "=f"(q[s][2]), "=f"(q[s][3]),
              "=f"(q[s][4]), "=f"(q[s][5]), "=f"(q[s][6]), "=f"(q[s][7])
            : "l"(qp[s]));
    }

    float r[6];
#pragma unroll
    for (int s = 0; s < 2; s++) {
        float wnw = (1.f - fy[s]) * (1.f - fx[s]);
        float wne = (1.f - fy[s]) * fx[s];
        float wsw = fy[s] * (1.f - fx[s]);
        float wse = fy[s] * fx[s];

        float2 nw = h2f(q[s][0]);
        float2 ne = h2f(q[s][2]);
        float2 sw = h2f(q[s][4]);
        float2 se = h2f(q[s][6]);
        float nwb = h2f(q[s][1]).x;
        float neb = h2f(q[s][3]).x;
        float swb = h2f(q[s][5]).x;
        float seb = h2f(q[s][7]).x;

        r[s * 3 + 0] = wnw * nw.x + wne * ne.x + wsw * sw.x + wse * se.x;
        r[s * 3 + 1] = wnw * nw.y + wne * ne.y + wsw * sw.y + wse * se.y;
        r[s * 3 + 2] = wnw * nwb  + wne * neb  + wsw * swb  + wse * seb;
    }

    // 6 floats per thread, streaming stores (evict-first), coalesced across warp.
    float2* o2 = reinterpret_cast<float2*>(out) + (size_t)t * 3;
    __stcs(&o2[0], make_float2(r[0], r[1]));
    __stcs(&o2[1], make_float2(r[2], r[3]));
    __stcs(&o2[2], make_float2(r[4], r[5]));
}

extern "C" void kernel_launch(void* const* d_in, const int* in_sizes, int n_in,
                              void* d_out, int out_size) {
    const float* source  = (const float*)d_in[0];
    const float* motions = (const float*)d_in[1];
    if (n_in >= 2 && in_sizes[0] != SRC_ELEMS) {
        source  = (const float*)d_in[1];
        motions = (const float*)d_in[0];
    }

    pack_src_kernel<<<(4 * COPYSZ + 255) / 256, 256>>>(source);

    const int nthreads = NMAPS * NPIX / 2;    // 2,883,584
    deform_kernel<<<nthreads / 256, 256>>>(motions, (float*)d_out);
}